// round 14
// baseline (speedup 1.0000x reference)
#include <cuda_runtime.h>
#include <cuda_bf16.h>
#include <cstdint>

#define NTHREADS 256
#define PRIME_X 73856093u
#define PRIME_Y 19349663u
#define PRIME_Z 83492791u

// ---------------- SMEM layout (bytes) ----------------
constexpr int OFF_TAB = 0;                       // fp32 tables, 11200 floats
constexpr int TAB_BYTES = 11200 * 4;             // 44800
constexpr int A_STRIDE = 144;                    // 72 bf16: 16B-aligned, bank-spread
constexpr int OFF_AHI = OFF_TAB + TAB_BYTES;     // 256 x 72 bf16
constexpr int OFF_ALO = OFF_AHI + 256 * A_STRIDE;
constexpr int OFF_BHI = OFF_ALO + 256 * A_STRIDE;  // 128 x 72 bf16 (B[n][k] = W1[k][n])
constexpr int OFF_BLO = OFF_BHI + 128 * A_STRIDE;
constexpr int OFF_B1  = OFF_BLO + 128 * A_STRIDE;  // 128 floats (bd1|0|bc1|0)
constexpr int OFF_W2D = OFF_B1 + 128 * 4;          // 64 floats
constexpr int OFF_W2C = OFF_W2D + 64 * 4;          // 3 x 64 floats
constexpr int SMEM_BYTES = OFF_W2C + 3 * 64 * 4;   // ~153.3 KB

// table offsets (floats) within OFF_TAB
constexpr int T0 = 0;            // 50 x 32
constexpr int T1 = T0 + 1600;    // 200 x 16
constexpr int T2 = T1 + 3200;    // 400 x 8
constexpr int T3 = T2 + 3200;    // 400 x 4
constexpr int T4 = T3 + 1600;    // 400 x 3 pad 4

__device__ __forceinline__ uint32_t smem_u32(const void* p) {
    uint32_t a;
    asm("{ .reg .u64 t; cvta.to.shared.u64 t, %1; cvt.u32.u64 %0, t; }" : "=r"(a) : "l"(p));
    return a;
}
__device__ __forceinline__ void ldm_x4(uint32_t (&r)[4], uint32_t addr) {
    asm volatile("ldmatrix.sync.aligned.m8n8.x4.shared.b16 {%0,%1,%2,%3}, [%4];"
                 : "=r"(r[0]), "=r"(r[1]), "=r"(r[2]), "=r"(r[3]) : "r"(addr));
}
__device__ __forceinline__ void mma_bf16(float (&d)[4], const uint32_t (&a)[4],
                                         uint32_t b0, uint32_t b1) {
    asm volatile(
        "mma.sync.aligned.m16n8k16.row.col.f32.bf16.bf16.f32 "
        "{%0,%1,%2,%3}, {%4,%5,%6,%7}, {%8,%9}, {%0,%1,%2,%3};"
        : "+f"(d[0]), "+f"(d[1]), "+f"(d[2]), "+f"(d[3])
        : "r"(a[0]), "r"(a[1]), "r"(a[2]), "r"(a[3]), "r"(b0), "r"(b1));
}
__device__ __forceinline__ void split_bf16(float f, uint16_t& hi, uint16_t& lo) {
    __nv_bfloat16 h = __float2bfloat16_rn(f);
    float rem = f - __bfloat162float(h);
    __nv_bfloat16 l = __float2bfloat16_rn(rem);
    hi = __bfloat16_as_ushort(h);
    lo = __bfloat16_as_ushort(l);
}

// ---------------- hash-grid encode (LDS.128 gathers) ------------------------
template <int H, int D, int S, int BASE>
__device__ __forceinline__ void encode_level(const float* __restrict__ sT,
                                             float px, float py, float pz,
                                             float (&feat)[63]) {
    float fx = floorf(px), fy = floorf(py), fz = floorf(pz);
    float rx = px - fx, ry = py - fy, rz = pz - fz;
    int fxi = (int)fx, fyi = (int)fy, fzi = (int)fz;
    int cxi = (int)ceilf(px), cyi = (int)ceilf(py), czi = (int)ceilf(pz);

    int hx0 = (int)((unsigned)fxi * PRIME_X);
    int hx1 = (int)((unsigned)cxi * PRIME_X);
    int hy0 = (int)((unsigned)fyi * PRIME_Y);
    int hy1 = (int)((unsigned)cyi * PRIME_Y);
    int hz0 = (int)((unsigned)fzi * PRIME_Z);
    int hz1 = (int)((unsigned)czi * PRIME_Z);

    // reference quirk: FLOOR corner weighted by r, CEIL corner by (1-r)
    float wx0 = rx, wx1 = 1.0f - rx;
    float wy0 = ry, wy1 = 1.0f - ry;
    float wz0 = rz, wz1 = 1.0f - rz;

    constexpr int D4 = (D + 3) / 4;
#pragma unroll
    for (int c = 0; c < 8; c++) {
        const int bi = (c >> 2) & 1, bj = (c >> 1) & 1, bk = c & 1;
        int v = (bi ? hx1 : hx0) ^ (bj ? hy1 : hy0) ^ (bk ? hz1 : hz0);
        int h = v % H;
        if (h < 0) h += H;  // Python-style nonneg mod
        float w = (bi ? wx1 : wx0) * (bj ? wy1 : wy0) * (bk ? wz1 : wz0);
        const float4* row = (const float4*)(sT + h * S);
#pragma unroll
        for (int q = 0; q < D4; q++) {
            float4 rv = row[q];
            feat[BASE + 4 * q + 0] = fmaf(w, rv.x, feat[BASE + 4 * q + 0]);
            if (4 * q + 1 < D) feat[BASE + 4 * q + 1] = fmaf(w, rv.y, feat[BASE + 4 * q + 1]);
            if (4 * q + 2 < D) feat[BASE + 4 * q + 2] = fmaf(w, rv.z, feat[BASE + 4 * q + 2]);
            if (4 * q + 3 < D) feat[BASE + 4 * q + 3] = fmaf(w, rv.w, feat[BASE + 4 * q + 3]);
        }
    }
}

template <int H, int D, int S>
__device__ __forceinline__ void load_table(float* dst, const float* __restrict__ src,
                                           int tid) {
    for (int i = tid; i < H * D; i += NTHREADS) {
        int r = i / D, c = i - r * D;
        dst[r * S + c] = src[i];
    }
}

__global__ void __launch_bounds__(NTHREADS)
nerf_mma_kernel(const float* __restrict__ x, const float* __restrict__ e0,
                const float* __restrict__ e1, const float* __restrict__ e2,
                const float* __restrict__ e3, const float* __restrict__ e4,
                const float* __restrict__ Wd1, const float* __restrict__ bd1,
                const float* __restrict__ Wd2, const float* __restrict__ bd2,
                const float* __restrict__ Wc1, const float* __restrict__ bc1,
                const float* __restrict__ Wc2, const float* __restrict__ bc2,
                float* __restrict__ out, int N) {
    extern __shared__ char smem[];
    float* smf = (float*)smem;
    const int tid = threadIdx.x;
    const int wid = tid >> 5;
    const int lane = tid & 31;
    const uint32_t sbase = smem_u32(smem);

    // ---- cooperative fill: tables (fp32) ----
    float* tabs = smf + OFF_TAB / 4;
    load_table<50, 32, 32>(tabs + T0, e0, tid);
    load_table<200, 16, 16>(tabs + T1, e1, tid);
    load_table<400, 8, 8>(tabs + T2, e2, tid);
    load_table<400, 4, 4>(tabs + T3, e3, tid);
    load_table<400, 3, 4>(tabs + T4, e4, tid);

    // ---- B: [n=0..127][k=0..63], B[n][k] = W1[k][n], bf16 hi/lo split ----
    for (int i = tid; i < 128 * 64; i += NTHREADS) {
        int n = i >> 6, k = i & 63;
        float v = 0.0f;
        if (k < 63 && (n & 63) < 63)
            v = (n < 64) ? Wd1[k * 63 + n] : Wc1[k * 63 + (n - 64)];
        uint16_t hi, lo;
        split_bf16(v, hi, lo);
        *(uint16_t*)(smem + OFF_BHI + n * A_STRIDE + k * 2) = hi;
        *(uint16_t*)(smem + OFF_BLO + n * A_STRIDE + k * 2) = lo;
    }
    // ---- b1 concat + W2 ----
    for (int i = tid; i < 128; i += NTHREADS) {
        float v = 0.0f;
        if (i < 63) v = bd1[i];
        else if (i >= 64 && i < 127) v = bc1[i - 64];
        smf[OFF_B1 / 4 + i] = v;
    }
    for (int i = tid; i < 64; i += NTHREADS)
        smf[OFF_W2D / 4 + i] = (i < 63) ? Wd2[i] : 0.0f;
    for (int i = tid; i < 3 * 64; i += NTHREADS) {
        int ch = i >> 6, o = i & 63;
        smf[OFF_W2C / 4 + i] = (o < 63) ? Wc2[o * 3 + ch] : 0.0f;
    }

    // ---- encode own point (1 pt/thread, 256 pts/block) ----
    __syncthreads();  // tables ready
    const int idx = blockIdx.x * 256 + tid;
    const int lidx = (idx < N) ? idx : 0;
    const float xv = x[lidx * 3 + 0];
    const float yv = x[lidx * 3 + 1];
    const float zv = x[lidx * 3 + 2];

    float feat[63];
#pragma unroll
    for (int i = 0; i < 63; i++) feat[i] = 0.0f;
    encode_level<50, 32, 32, 0>(tabs + T0, xv, yv, zv, feat);
    encode_level<200, 16, 16, 32>(tabs + T1, xv * 2.0f, yv * 2.0f, zv * 2.0f, feat);
    encode_level<400, 8, 8, 48>(tabs + T2, xv * 4.0f, yv * 4.0f, zv * 4.0f, feat);
    encode_level<400, 4, 4, 56>(tabs + T3, xv * 8.0f, yv * 8.0f, zv * 8.0f, feat);
    encode_level<400, 3, 4, 60>(tabs + T4, __fdiv_rn(xv, 0.05f),
                                __fdiv_rn(yv, 0.05f), __fdiv_rn(zv, 0.05f), feat);

    // ---- stage A row (bf16 hi/lo): row = tid ----
    {
        char* ahi = smem + OFF_AHI + tid * A_STRIDE;
        char* alo = smem + OFF_ALO + tid * A_STRIDE;
#pragma unroll
        for (int k = 0; k < 64; k += 2) {
            float f0 = (k < 63) ? feat[k] : 0.0f;
            float f1 = (k + 1 < 63) ? feat[k + 1] : 0.0f;
            uint16_t h0, l0, h1, l1;
            split_bf16(f0, h0, l0);
            split_bf16(f1, h1, l1);
            *(uint32_t*)(ahi + k * 2) = (uint32_t)h0 | ((uint32_t)h1 << 16);
            *(uint32_t*)(alo + k * 2) = (uint32_t)l0 | ((uint32_t)l1 << 16);
        }
    }
    __syncthreads();

    // ---- warp GEMM: 32 pts x 128 cols, K=64, bf16-split (hh + hl + lh) ----
    const int m0 = wid * 32;
    float acc[2][16][4];
#pragma unroll
    for (int mt = 0; mt < 2; mt++)
#pragma unroll
        for (int nt = 0; nt < 16; nt++)
#pragma unroll
            for (int e = 0; e < 4; e++) acc[mt][nt][e] = 0.0f;

    // lane-addressing offsets
    const int a_row = (lane & 15);
    const int a_kadd = (lane >> 4) * 8;
    const int b_row = (lane & 7) + ((lane >> 4) * 8);
    const int b_kadd = ((lane >> 3) & 1) * 8;

#pragma unroll
    for (int ks = 0; ks < 4; ks++) {
        const int k0 = ks * 16;
        uint32_t ah[2][4], al[2][4];
#pragma unroll
        for (int mt = 0; mt < 2; mt++) {
            const int row = m0 + mt * 16 + a_row;
            const uint32_t off = (uint32_t)(row * A_STRIDE + (k0 + a_kadd) * 2);
            ldm_x4(ah[mt], sbase + OFF_AHI + off);
            ldm_x4(al[mt], sbase + OFF_ALO + off);
        }
#pragma unroll
        for (int nt2 = 0; nt2 < 8; nt2++) {
            const int n0 = nt2 * 16;
            const uint32_t boff = (uint32_t)((n0 + b_row) * A_STRIDE + (k0 + b_kadd) * 2);
            uint32_t bh[4], bl[4];
            ldm_x4(bh, sbase + OFF_BHI + boff);
            ldm_x4(bl, sbase + OFF_BLO + boff);
#pragma unroll
            for (int half = 0; half < 2; half++) {
                const int nt = nt2 * 2 + half;
                const uint32_t bh0 = bh[half * 2], bh1 = bh[half * 2 + 1];
                const uint32_t bl0 = bl[half * 2], bl1 = bl[half * 2 + 1];
#pragma unroll
                for (int mt = 0; mt < 2; mt++) {
                    mma_bf16(acc[mt][nt], ah[mt], bh0, bh1);
                    mma_bf16(acc[mt][nt], ah[mt], bl0, bl1);
                    mma_bf16(acc[mt][nt], al[mt], bh0, bh1);
                }
            }
        }
    }

    // ---- epilogue: bias+relu+second layer, quad-reduce, store ----
    {
        const int quad = lane >> 2;   // row group 0..7
        const int qt = lane & 3;      // col group
        const float* b1 = smf + OFF_B1 / 4;
        const float* w2d = smf + OFF_W2D / 4;
        const float* w2c = smf + OFF_W2C / 4;
        const float bd2v = bd2[0];
        const float bc20 = bc2[0], bc21 = bc2[1], bc22 = bc2[2];

#pragma unroll
        for (int mt = 0; mt < 2; mt++) {
            float sd[2] = {0.0f, 0.0f};
            float sc[3][2] = {{0, 0}, {0, 0}, {0, 0}};
#pragma unroll
            for (int nt = 0; nt < 16; nt++) {
                const int col0 = nt * 8 + qt * 2;
                const float b1_0 = b1[col0], b1_1 = b1[col0 + 1];
                float h00 = fmaxf(acc[mt][nt][0] + b1_0, 0.0f);
                float h01 = fmaxf(acc[mt][nt][1] + b1_1, 0.0f);
                float h10 = fmaxf(acc[mt][nt][2] + b1_0, 0.0f);
                float h11 = fmaxf(acc[mt][nt][3] + b1_1, 0.0f);
                if (nt < 8) {
                    const float w0 = w2d[col0], w1 = w2d[col0 + 1];
                    sd[0] = fmaf(h00, w0, fmaf(h01, w1, sd[0]));
                    sd[1] = fmaf(h10, w0, fmaf(h11, w1, sd[1]));
                } else {
                    const int cc = col0 - 64;
#pragma unroll
                    for (int ch = 0; ch < 3; ch++) {
                        const float w0 = w2c[ch * 64 + cc], w1 = w2c[ch * 64 + cc + 1];
                        sc[ch][0] = fmaf(h00, w0, fmaf(h01, w1, sc[ch][0]));
                        sc[ch][1] = fmaf(h10, w0, fmaf(h11, w1, sc[ch][1]));
                    }
                }
            }
            // quad reduction (lanes 4g..4g+3 hold disjoint cols of same rows)
#pragma unroll
            for (int r = 0; r < 2; r++) {
                sd[r] += __shfl_xor_sync(0xffffffffu, sd[r], 1);
                sd[r] += __shfl_xor_sync(0xffffffffu, sd[r], 2);
#pragma unroll
                for (int ch = 0; ch < 3; ch++) {
                    sc[ch][r] += __shfl_xor_sync(0xffffffffu, sc[ch][r], 1);
                    sc[ch][r] += __shfl_xor_sync(0xffffffffu, sc[ch][r], 2);
                }
            }
            if (qt == 0) {
#pragma unroll
                for (int r = 0; r < 2; r++) {
                    const int pt = blockIdx.x * 256 + m0 + mt * 16 + quad + r * 8;
                    if (pt < N) {
                        out[pt] = sd[r] + bd2v;
                        out[N + pt * 3 + 0] = sc[0][r] + bc20;
                        out[N + pt * 3 + 1] = sc[1][r] + bc21;
                        out[N + pt * 3 + 2] = sc[2][r] + bc22;
                    }
                }
            }
        }
    }
}

extern "C" void kernel_launch(void* const* d_in, const int* in_sizes, int n_in,
                              void* d_out, int out_size) {
    const float* x = (const float*)d_in[0];
    const float* e0 = (const float*)d_in[1];
    const float* e1 = (const float*)d_in[2];
    const float* e2 = (const float*)d_in[3];
    const float* e3 = (const float*)d_in[4];
    const float* e4 = (const float*)d_in[5];
    const float* Wd1 = (const float*)d_in[6];
    const float* bd1 = (const float*)d_in[7];
    const float* Wd2 = (const float*)d_in[8];
    const float* bd2 = (const float*)d_in[9];
    const float* Wc1 = (const float*)d_in[10];
    const float* bc1 = (const float*)d_in[11];
    const float* Wc2 = (const float*)d_in[12];
    const float* bc2 = (const float*)d_in[13];

    const int N = in_sizes[0] / 3;
    float* out = (float*)d_out;

    cudaFuncSetAttribute(nerf_mma_kernel,
                         cudaFuncAttributeMaxDynamicSharedMemorySize, SMEM_BYTES);

    const int grid = (N + 255) / 256;
    nerf_mma_kernel<<<grid, NTHREADS, SMEM_BYTES>>>(
        x, e0, e1, e2, e3, e4, Wd1, bd1, Wd2, bd2, Wc1, bc1, Wc2, bc2, out, N);
}